// round 16
// baseline (speedup 1.0000x reference)
#include <cuda_runtime.h>
#include <cstdint>
#include <cmath>

// ---------------------------------------------------------------------------
// Instant-NGP HashEncoder: B=2,097,152 points, D=3, L=16, C=2,
// base_res=16, desired=2048, log2_hashmap=19.
//
// R16: Morton bucketing refined.
//  - 64^3 buckets (finer locality: levels <=12 L1-resident per CTA region)
//  - hist/scatter batched 4 points/thread (atomic latency hiding)
//  - scatter emits packed float4(x,y,z,idx) -> encode coord reads coalesced
//  - encode: XOR-chunk hashed merging (__ldg), dense pair table, host scales,
//    8 threads/point, output written to original row (deterministic).
// ---------------------------------------------------------------------------

#define NLEVELS 16
#define HASH_MASK 524287u
#define P2 2654435761u
#define P3 805459861u
#define DENSE_PARAMS 330952       // OFFSETS[5]: entries of dense levels 0..4
#define MAXB (1 << 21)            // 2,097,152 points
#define NBUCKETS (64*64*64)       // 262,144 Morton buckets

// level tables (verified: total params == 6,098,120 matches reference)
__device__ const unsigned g_res[NLEVELS] = {16u, 23u, 31u, 43u, 59u, 81u, 112u, 154u,
                                            213u, 295u, 407u, 562u, 777u, 1073u, 1483u, 2048u};
__device__ const unsigned g_off[NLEVELS] = {0u, 4096u, 16264u, 46056u, 125568u,
                                            330952u, 855240u, 1379528u, 1903816u,
                                            2428104u, 2952392u, 3476680u, 4000968u,
                                            4525256u, 5049544u, 5573832u};

struct Scales { float s[NLEVELS]; };

__device__ float4 g_dpair[DENSE_PARAMS];  // dense pair table
__device__ unsigned g_hist[NBUCKETS];
__device__ unsigned g_offsets[NBUCKETS];
__device__ float4 g_pts[MAXB];            // Morton-ordered (x,y,z,bitcast(idx))

// ---- Morton helpers -------------------------------------------------------
__device__ __forceinline__ unsigned part1by2(unsigned v) {
    v &= 0x3FFu;
    v = (v | (v << 16)) & 0x030000FFu;
    v = (v | (v << 8))  & 0x0300F00Fu;
    v = (v | (v << 4))  & 0x030C30C3u;
    v = (v | (v << 2))  & 0x09249249u;
    return v;
}

__device__ __forceinline__ unsigned bucket_of(float x, float y, float z) {
    unsigned bx = min((unsigned)(x * 64.0f), 63u);
    unsigned by = min((unsigned)(y * 64.0f), 63u);
    unsigned bz = min((unsigned)(z * 64.0f), 63u);
    return part1by2(bx) | (part1by2(by) << 1) | (part1by2(bz) << 2);
}

// ---- permutation pipeline -------------------------------------------------
__global__ __launch_bounds__(256)
void zero_hist_kernel() {
    int i = blockIdx.x * blockDim.x + threadIdx.x;
    if (i < NBUCKETS) g_hist[i] = 0u;
}

// 4 points per thread: coords read as 3 coalesced float4s
__global__ __launch_bounds__(256)
void hist_kernel(const float4* __restrict__ in4, int B) {
    const int q = blockIdx.x * blockDim.x + threadIdx.x;  // quad index
    const int p0 = q * 4;
    if (p0 >= B) return;
    const float4 a = __ldg(&in4[q * 3 + 0]);
    const float4 b = __ldg(&in4[q * 3 + 1]);
    const float4 c = __ldg(&in4[q * 3 + 2]);
    // 4 independent atomics in flight
    atomicAdd(&g_hist[bucket_of(a.x, a.y, a.z)], 1u);
    atomicAdd(&g_hist[bucket_of(a.w, b.x, b.y)], 1u);
    atomicAdd(&g_hist[bucket_of(b.z, b.w, c.x)], 1u);
    atomicAdd(&g_hist[bucket_of(c.y, c.z, c.w)], 1u);
}

// exclusive scan: 1024 threads x 256 buckets each, two-pass per thread
__global__ __launch_bounds__(1024)
void scan_kernel() {
    __shared__ unsigned sh[2][1024];
    const int tid = threadIdx.x;
    const int base = tid * (NBUCKETS / 1024);   // 256 buckets per thread

    unsigned run = 0;
    for (int i = 0; i < NBUCKETS / 1024; ++i)
        run += g_hist[base + i];
    sh[0][tid] = run;
    __syncthreads();

    int src = 0;
    for (int off = 1; off < 1024; off <<= 1) {
        const int dst = 1 - src;
        unsigned v = sh[src][tid];
        if (tid >= off) v += sh[src][tid - off];
        sh[dst][tid] = v;
        __syncthreads();
        src = dst;
    }
    unsigned run2 = (tid == 0) ? 0u : sh[src][tid - 1];  // exclusive prefix

    for (int i = 0; i < NBUCKETS / 1024; ++i) {
        g_offsets[base + i] = run2;
        run2 += g_hist[base + i];
    }
}

__global__ __launch_bounds__(256)
void scatter_kernel(const float4* __restrict__ in4, int B) {
    const int q = blockIdx.x * blockDim.x + threadIdx.x;
    const int p0 = q * 4;
    if (p0 >= B) return;
    const float4 a = __ldg(&in4[q * 3 + 0]);
    const float4 b = __ldg(&in4[q * 3 + 1]);
    const float4 c = __ldg(&in4[q * 3 + 2]);

    float xs[4] = {a.x, a.w, b.z, c.y};
    float ys[4] = {a.y, b.x, b.w, c.z};
    float zs[4] = {a.z, b.y, c.x, c.w};
#pragma unroll
    for (int k = 0; k < 4; ++k) {
        const unsigned pos = atomicAdd(&g_offsets[bucket_of(xs[k], ys[k], zs[k])], 1u);
        g_pts[pos] = make_float4(xs[k], ys[k], zs[k], __int_as_float(p0 + k));
    }
}

// ---- dense pair table -----------------------------------------------------
__global__ __launch_bounds__(256)
void build_dense_pairs_kernel(const float2* __restrict__ emb) {
    int i = blockIdx.x * blockDim.x + threadIdx.x;
    if (i >= DENSE_PARAMS) return;
    const float2 a = __ldg(&emb[i]);
    const float2 b = __ldg(&emb[i + 1]);
    g_dpair[i] = make_float4(a.x, a.y, b.x, b.y);
}

// ---- encode ---------------------------------------------------------------
__device__ __forceinline__ void encode_level(int l, float scale,
                                             float x, float y, float z,
                                             const float2* __restrict__ emb,
                                             float& ax, float& ay)
{
    const unsigned res = __ldg(&g_res[l]);
    const unsigned rm1 = res - 1u;
    const unsigned off = __ldg(&g_off[l]);

    const float px = __fadd_rn(__fmul_rn(x, scale), 0.5f);
    const float py = __fadd_rn(__fmul_rn(y, scale), 0.5f);
    const float pz = __fadd_rn(__fmul_rn(z, scale), 0.5f);

    const float fxg = floorf(px), fyg = floorf(py), fzg = floorf(pz);
    const float fx = px - fxg, fy = py - fyg, fz = pz - fzg;
    const unsigned gx = (unsigned)fxg, gy = (unsigned)fyg, gz = (unsigned)fzg;

    const float wx0 = 1.0f - fx, wx1 = fx;
    const float wy_[2] = {1.0f - fy, fy};
    const float wz_[2] = {1.0f - fz, fz};

    const unsigned cx0 = min(gx, rm1), cx1 = min(gx + 1u, rm1);
    const unsigned cy0 = min(gy, rm1), cy1 = min(gy + 1u, rm1);
    const unsigned cz0 = min(gz, rm1), cz1 = min(gz + 1u, rm1);

    ax = 0.0f; ay = 0.0f;

    if (l >= 5) {
        // hashed: XOR-chunk merging, L1-cached loads
        const unsigned hy0 = cy0 * P2, hy1 = cy1 * P2;
        const unsigned hz0 = cz0 * P3, hz1 = cz1 * P3;
        const float2* __restrict__ tab = emb + off;
        const float4* __restrict__ tab4 = reinterpret_cast<const float4*>(tab);
        unsigned byz[4] = {hy0 ^ hz0, hy1 ^ hz0, hy0 ^ hz1, hy1 ^ hz1};
#pragma unroll
        for (int p = 0; p < 4; ++p) {
            const unsigned by = p & 1u, bz = (p >> 1) & 1u;
            const float wyz = wy_[by] * wz_[bz];
            const float w0 = wx0 * wyz, w1 = wx1 * wyz;
            const unsigned i0 = (cx0 ^ byz[p]) & HASH_MASK;
            const unsigned i1 = (cx1 ^ byz[p]) & HASH_MASK;
            if ((i0 ^ i1) == 1u) {
                const float4 q = __ldg(tab4 + (i0 >> 1));
                const bool sw = (i0 & 1u);
                const float e0x = sw ? q.z : q.x;
                const float e0y = sw ? q.w : q.y;
                const float e1x = sw ? q.x : q.z;
                const float e1y = sw ? q.y : q.w;
                ax = fmaf(w0, e0x, ax);
                ay = fmaf(w0, e0y, ay);
                ax = fmaf(w1, e1x, ax);
                ay = fmaf(w1, e1y, ay);
            } else {
                const float2 e0 = __ldg(tab + i0);
                const float2 e1 = __ldg(tab + i1);
                ax = fmaf(w0, e0.x, ax);
                ay = fmaf(w0, e0.y, ay);
                ax = fmaf(w1, e1.x, ax);
                ay = fmaf(w1, e1.y, ay);
            }
        }
    } else {
        // dense: pair table, 100% merge
        const unsigned ry0 = cy0 * res, ry1 = cy1 * res;
        const unsigned rz0 = cz0 * res * res, rz1 = cz1 * res * res;
        unsigned bases[4] = {ry0 + rz0 + off, ry1 + rz0 + off,
                             ry0 + rz1 + off, ry1 + rz1 + off};
        const bool noclamp = (cx1 == cx0 + 1u);
#pragma unroll
        for (int p = 0; p < 4; ++p) {
            const unsigned by = p & 1u, bz = (p >> 1) & 1u;
            const float wyz = wy_[by] * wz_[bz];
            const float w0 = wx0 * wyz, w1 = wx1 * wyz;
            const float4 q = __ldg(&g_dpair[cx0 + bases[p]]);
            if (noclamp) {
                ax = fmaf(w0, q.x, ax);
                ay = fmaf(w0, q.y, ay);
                ax = fmaf(w1, q.z, ax);
                ay = fmaf(w1, q.w, ay);
            } else {
                const float w = w0 + w1;
                ax = fmaf(w, q.x, ax);
                ay = fmaf(w, q.y, ay);
            }
        }
    }
}

__global__ __launch_bounds__(256)
void hash_encode_kernel8(const float2* __restrict__ emb,
                         float* __restrict__ out,
                         Scales sc,
                         int B)
{
    const int t = blockIdx.x * blockDim.x + threadIdx.x;
    const int j = t >> 3;              // position in Morton order
    const int slot = t & 7;
    if (j >= B) return;

    // one coalesced float4 per point (8 lanes broadcast)
    const float4 pt = __ldg(&g_pts[j]);
    const float x = pt.x, y = pt.y, z = pt.z;
    const int point = __float_as_int(pt.w);

    const int l0 = 2 * slot;
    float a0x, a0y, a1x, a1y;
    encode_level(l0 + 0, sc.s[l0 + 0], x, y, z, emb, a0x, a0y);
    encode_level(l0 + 1, sc.s[l0 + 1], x, y, z, emb, a1x, a1y);

    // write to the point's ORIGINAL output row (128B contiguous per point)
    float4* __restrict__ dst =
        reinterpret_cast<float4*>(out + (size_t)point * (2 * NLEVELS)) + slot;
    *dst = make_float4(a0x, a0y, a1x, a1y);
}

extern "C" void kernel_launch(void* const* d_in, const int* in_sizes, int n_in,
                              void* d_out, int out_size) {
    const float*  inputs = (const float*)d_in[0];   // [B, 3]
    const float2* emb    = (const float2*)d_in[1];  // [TOTAL_PARAMS, 2]
    float*        out    = (float*)d_out;           // [B, 32]

    const int B = in_sizes[0] / 3;
    const float4* in4 = (const float4*)inputs;      // B*3 floats = (B/4)*3 float4

    Scales sc;
    for (int l = 0; l < NLEVELS; ++l) {
        double s = exp2((double)l * (7.0 / 15.0)) * 16.0 - 1.0;
        sc.s[l] = (float)s;
    }

    const int T = 256;
    const int quads = (B + 3) / 4;

    zero_hist_kernel<<<(NBUCKETS + T - 1) / T, T>>>();
    hist_kernel<<<(quads + T - 1) / T, T>>>(in4, B);
    scan_kernel<<<1, 1024>>>();
    scatter_kernel<<<(quads + T - 1) / T, T>>>(in4, B);

    build_dense_pairs_kernel<<<(DENSE_PARAMS + T - 1) / T, T>>>(emb);

    const long long total = (long long)B * 8;
    hash_encode_kernel8<<<(int)((total + T - 1) / T), T>>>(emb, out, sc, B);
}